// round 17
// baseline (speedup 1.0000x reference)
#include <cuda_runtime.h>
#include <cuda_fp16.h>
#include <cstdint>

#define N_E    8192
#define E_DIM  256
#define N_TOK  32768

#define OFF_ZQ   0
#define OFF_IDX  8388608
#define OFF_LOSS 8421376
#define OFF_NEMB 8421377

#define TH_MARGIN 4.0e-2f
#define BM     256
#define BN     64
#define NSTG   128               // 8192 / 64
#define ROWSTR 528u

// dynamic smem layout (bytes)
#define SM_A   0u                // 256 x 528 = 135168
#define SM_B   135168u           // 2 stages x 64 x 528 = 67584
#define SM_EN  202752u           // 2 stages x 256B
#define SM_ZN  203264u           // 256 x 4B
#define SM_DYN 204800

// ---- device scratch (no allocations allowed) ----
__device__ float g_bins[N_E];
__device__ float g_dw[N_E * E_DIM];
__device__ float g_eN[N_E];
__device__ float g_loss;
__device__ int   g_ucount;
__device__ int   g_idxi[N_TOK];
__device__ float g_zn[N_TOK];
__device__ int   g_urows[N_TOK];
__device__ int   g_ucand[N_TOK * 32];
__device__ __half g_eh[N_E * E_DIM];

// ---------------- PTX helpers ----------------
__device__ __forceinline__ uint32_t smem_u32(const void* p) {
    uint32_t a;
    asm("{ .reg .u64 t; cvta.to.shared.u64 t, %1; cvt.u32.u64 %0, t; }" : "=r"(a) : "l"(p));
    return a;
}
__device__ __forceinline__ void cpa16(uint32_t dst, const void* src) {
    asm volatile("cp.async.cg.shared.global [%0], [%1], 16;" :: "r"(dst), "l"(src) : "memory");
}
__device__ __forceinline__ void ldm4(uint32_t* r, uint32_t a) {
    asm volatile("ldmatrix.sync.aligned.m8n8.x4.shared.b16 {%0,%1,%2,%3}, [%4];"
                 : "=r"(r[0]), "=r"(r[1]), "=r"(r[2]), "=r"(r[3]) : "r"(a));
}
__device__ __forceinline__ void mma16816h(uint32_t* c, const uint32_t* a, const uint32_t* b) {
    asm volatile(
        "mma.sync.aligned.m16n8k16.row.col.f16.f16.f16.f16 "
        "{%0,%1}, {%2,%3,%4,%5}, {%6,%7}, {%0,%1};"
        : "+r"(c[0]), "+r"(c[1])
        : "r"(a[0]), "r"(a[1]), "r"(a[2]), "r"(a[3]), "r"(b[0]), "r"(b[1]));
}
__device__ __forceinline__ void lds128(uint32_t* r, uint32_t a) {
    asm volatile("ld.shared.v4.u32 {%0,%1,%2,%3}, [%4];"
                 : "=r"(r[0]), "=r"(r[1]), "=r"(r[2]), "=r"(r[3]) : "r"(a));
}

// ============================================================
// K1 (fused init+prep)
// ============================================================
__global__ void k_prep(const float* __restrict__ emb) {
    int gid = blockIdx.x * blockDim.x + threadIdx.x;
    g_dw[gid] = 0.0f;
    g_eh[gid] = __float2half_rn(emb[gid]);
    if (gid < N_E) {
        g_bins[gid] = 0.0f;
        const float4* e4 = (const float4*)(emb + (size_t)gid * E_DIM);
        float s = 0.0f;
        #pragma unroll 8
        for (int i = 0; i < 64; i++) {
            float4 v = e4[i];
            s = __fadd_rn(s, __fmul_rn(v.x, v.x));
            s = __fadd_rn(s, __fmul_rn(v.y, v.y));
            s = __fadd_rn(s, __fmul_rn(v.z, v.z));
            s = __fadd_rn(s, __fmul_rn(v.w, v.w));
        }
        g_eN[gid] = s;
    }
    if (gid == 0) { g_loss = 0.0f; g_ucount = 0; }
}

// ============================================================
// K3: hybrid — warps 0-11 HMMA on cols 0-47, warps 12-15 HFMA2 on cols 48-63
// ============================================================
__device__ __forceinline__ void prefetchB(uint32_t sb, int tid, int nt) {
    int s = nt & 1;
    int row = tid >> 3;
    int q   = tid & 7;
    const char* src = (const char*)g_eh + ((size_t)nt * BN + row) * 512 + (size_t)q * 64;
    uint32_t dst = sb + SM_B + (uint32_t)s * 33792u + (uint32_t)row * ROWSTR + (uint32_t)q * 64;
    #pragma unroll
    for (int j = 0; j < 4; j++) cpa16(dst + j * 16, src + j * 16);
    if (tid < 16) cpa16(sb + SM_EN + (uint32_t)s * 256 + tid * 16,
                        (const char*)g_eN + (size_t)nt * 256 + tid * 16);
}

__global__ __launch_bounds__(512, 1)
void k_mma(const float* __restrict__ z) {
    extern __shared__ char smraw[];
    const uint32_t sb = smem_u32(smraw);
    const int tid  = threadIdx.x;
    const int lane = tid & 31;
    const int wid  = tid >> 5;           // 0..15
    const int row0 = blockIdx.x * BM;

    prefetchB(sb, tid, 0);
    asm volatile("cp.async.commit_group;" ::: "memory");

    // ---- prologue: all 256 rows -> f16 A in smem, exact zn ----
    if (tid < BM) {
        const float4* zr4 = (const float4*)(z + (size_t)(row0 + tid) * E_DIM);
        uint32_t* ap = (uint32_t*)(smraw + SM_A + (uint32_t)tid * ROWSTR);
        float zn = 0.0f;
        #pragma unroll 4
        for (int i = 0; i < 64; i++) {
            float4 v = zr4[i];
            zn = __fadd_rn(zn, __fmul_rn(v.x, v.x));
            zn = __fadd_rn(zn, __fmul_rn(v.y, v.y));
            zn = __fadd_rn(zn, __fmul_rn(v.z, v.z));
            zn = __fadd_rn(zn, __fmul_rn(v.w, v.w));
            __half h0 = __float2half_rn(v.x), h1 = __float2half_rn(v.y);
            __half h2 = __float2half_rn(v.z), h3 = __float2half_rn(v.w);
            ap[i * 2 + 0] = ((uint32_t)__half_as_ushort(h1) << 16) | __half_as_ushort(h0);
            ap[i * 2 + 1] = ((uint32_t)__half_as_ushort(h3) << 16) | __half_as_ushort(h2);
        }
        *(float*)(smraw + SM_ZN + tid * 4) = zn;
        g_zn[row0 + tid] = zn;
    }
    __syncthreads();

    // -------- per-warp setup --------
    const int isH = (wid < 12);
    // HMMA role
    const int mw  = wid & 3;             // also SMSP id
    const int nc  = wid >> 2;            // 0..2
    const int gid = lane >> 2;
    const int tig = lane & 3;
    uint32_t aA[4], bA = 0;
    float znH[8];
    if (isH) {
        uint32_t arow = (uint32_t)(lane & 15);
        uint32_t ab   = ((uint32_t)(lane >> 4) & 1) * 16;
        #pragma unroll
        for (int mt = 0; mt < 4; mt++)
            aA[mt] = sb + SM_A + ((uint32_t)(mw * 64 + mt * 16) + arow) * ROWSTR + ab;
        bA = sb + SM_B + ((uint32_t)(nc * 16) + arow) * ROWSTR + ab;
        #pragma unroll
        for (int sl = 0; sl < 8; sl++) {
            int r = mw * 64 + (sl >> 1) * 16 + (sl & 1) * 8 + gid;
            znH[sl] = *(const float*)(smraw + SM_ZN + r * 4);
        }
    }
    // HFMA2 role
    const int fw = wid - 12;             // 0..3 (== SMSP id)
    const int fg = lane >> 2;            // 0..7 row-group
    const int fc = lane & 3;             // 0..3 col-group
    uint32_t aBase = 0, bBase = 0;
    float znF[8];
    if (!isH) {
        aBase = sb + SM_A + (uint32_t)(fw * 64 + fg * 8) * ROWSTR;
        bBase = sb + SM_B + (uint32_t)(48 + fc * 4) * ROWSTR;
        #pragma unroll
        for (int rr = 0; rr < 8; rr++)
            znF[rr] = *(const float*)(smraw + SM_ZN + (fw * 64 + fg * 8 + rr) * 4);
    }

    float tb0[8], tb1[8];
    int   ti0[8], ti1[8];
    #pragma unroll
    for (int sl = 0; sl < 8; sl++) { tb0[sl] = 3.4e38f; tb1[sl] = 3.4e38f; ti0[sl] = 0; ti1[sl] = 0; }

    for (int nt = 0; nt < NSTG; nt++) {
        if (nt + 1 < NSTG) {
            prefetchB(sb, tid, nt + 1);
            asm volatile("cp.async.commit_group;" ::: "memory");
            asm volatile("cp.async.wait_group 1;" ::: "memory");
        } else {
            asm volatile("cp.async.wait_group 0;" ::: "memory");
        }
        __syncthreads();

        const uint32_t sof = (uint32_t)(nt & 1) * 33792u;
        const float* eNs = (const float*)(smraw + SM_EN + (uint32_t)(nt & 1) * 256);

        if (isH) {
            uint32_t acc[4][2][2];       // [m-tile][n-tile] f16x2 pair
            #pragma unroll
            for (int mt = 0; mt < 4; mt++)
                #pragma unroll
                for (int q = 0; q < 2; q++) { acc[mt][q][0] = 0u; acc[mt][q][1] = 0u; }

            #pragma unroll
            for (int kk = 0; kk < 16; kk++) {
                uint32_t kb = (uint32_t)kk * 32;
                uint32_t bw[4];
                ldm4(bw, bA + sof + kb);
                #pragma unroll
                for (int mt = 0; mt < 4; mt++) {
                    uint32_t af[4];
                    ldm4(af, aA[mt] + kb);
                    #pragma unroll
                    for (int q = 0; q < 2; q++) {
                        uint32_t bf[2] = { bw[q], bw[q + 2] };
                        mma16816h(acc[mt][q], af, bf);
                    }
                }
            }
            // distances + top2 per slot (cols ascending)
            #pragma unroll
            for (int q = 0; q < 2; q++) {
                int colb = nt * BN + nc * 16 + q * 8 + 2 * tig;
                float e0 = eNs[nc * 16 + q * 8 + 2 * tig];
                float e1 = eNs[nc * 16 + q * 8 + 2 * tig + 1];
                #pragma unroll
                for (int mt = 0; mt < 4; mt++)
                    #pragma unroll
                    for (int hh = 0; hh < 2; hh++) {
                        int sl = mt * 2 + hh;
                        __half2 hv = *(__half2*)&acc[mt][q][hh];
                        float d0 = __fmaf_rn(-2.0f, __half2float(__low2half(hv)),  znH[sl] + e0);
                        float d1 = __fmaf_rn(-2.0f, __half2float(__high2half(hv)), znH[sl] + e1);
                        if (d0 < tb1[sl]) {
                            if (d0 < tb0[sl]) { tb1[sl]=tb0[sl]; ti1[sl]=ti0[sl]; tb0[sl]=d0; ti0[sl]=colb; }
                            else              { tb1[sl]=d0; ti1[sl]=colb; }
                        }
                        if (d1 < tb1[sl]) {
                            if (d1 < tb0[sl]) { tb1[sl]=tb0[sl]; ti1[sl]=ti0[sl]; tb0[sl]=d1; ti0[sl]=colb+1; }
                            else              { tb1[sl]=d1; ti1[sl]=colb+1; }
                        }
                    }
            }
        } else {
            __half2 acc[8][4];
            #pragma unroll
            for (int rr = 0; rr < 8; rr++)
                #pragma unroll
                for (int j = 0; j < 4; j++) acc[rr][j] = __float2half2_rn(0.0f);

            #pragma unroll 2
            for (int ck = 0; ck < 32; ck++) {
                uint32_t koff = (uint32_t)((ck + fg) & 31) * 16;   // per-lane k rotation
                uint32_t b4[4][4];
                #pragma unroll
                for (int j = 0; j < 4; j++)
                    lds128(b4[j], bBase + sof + (uint32_t)j * ROWSTR + koff);
                #pragma unroll
                for (int rr = 0; rr < 8; rr++) {
                    uint32_t a4[4];
                    lds128(a4, aBase + (uint32_t)rr * ROWSTR + koff);
                    #pragma unroll
                    for (int j = 0; j < 4; j++) {
                        acc[rr][j] = __hfma2(*(__half2*)&a4[0], *(__half2*)&b4[j][0], acc[rr][j]);
                        acc[rr][j] = __hfma2(*(__half2*)&a4[1], *(__half2*)&b4[j][1], acc[rr][j]);
                        acc[rr][j] = __hfma2(*(__half2*)&a4[2], *(__half2*)&b4[j][2], acc[rr][j]);
                        acc[rr][j] = __hfma2(*(__half2*)&a4[3], *(__half2*)&b4[j][3], acc[rr][j]);
                    }
                }
            }
            // distances + top2 per row slot (cols ascending j)
            #pragma unroll
            for (int j = 0; j < 4; j++) {
                int cc  = 48 + fc * 4 + j;
                int col = nt * BN + cc;
                float ec = eNs[cc];
                #pragma unroll
                for (int rr = 0; rr < 8; rr++) {
                    float dot = __fadd_rn(__half2float(__low2half(acc[rr][j])),
                                          __half2float(__high2half(acc[rr][j])));
                    float d = __fmaf_rn(-2.0f, dot, znF[rr] + ec);
                    if (d < tb1[rr]) {
                        if (d < tb0[rr]) { tb1[rr]=tb0[rr]; ti1[rr]=ti0[rr]; tb0[rr]=d; ti0[rr]=col; }
                        else             { tb1[rr]=d; ti1[rr]=col; }
                    }
                }
            }
        }
        __syncthreads();
    }

    // ---- candidate table [256][32] in reused A region ----
    float* tD = (float*)smraw;
    int*   tI = (int*)(smraw + 32768);
    if (isH) {
        #pragma unroll
        for (int sl = 0; sl < 8; sl++) {
            int r = mw * 64 + (sl >> 1) * 16 + (sl & 1) * 8 + gid;
            int o = (nc * 4 + tig) * 2;          // 0..23
            tD[r * 32 + o + 0] = tb0[sl]; tI[r * 32 + o + 0] = ti0[sl];
            tD[r * 32 + o + 1] = tb1[sl]; tI[r * 32 + o + 1] = ti1[sl];
        }
    } else {
        #pragma unroll
        for (int rr = 0; rr < 8; rr++) {
            int r = fw * 64 + fg * 8 + rr;
            int o = 24 + fc * 2;                 // 24..31
            tD[r * 32 + o + 0] = tb0[rr]; tI[r * 32 + o + 0] = ti0[rr];
            tD[r * 32 + o + 1] = tb1[rr]; tI[r * 32 + o + 1] = ti1[rr];
        }
    }
    __syncthreads();

    if (tid < BM) {
        float b0 = 3.4e38f, b1 = 3.4e38f;
        int   i0 = 0x7FFFFFFF, i1 = 0x7FFFFFFF;
        #pragma unroll 8
        for (int q = 0; q < 32; q++) {
            float d = tD[tid * 32 + q];
            int   c = tI[tid * 32 + q];
            if (d < b0 || (d == b0 && c < i0)) { b1 = b0; i1 = i0; b0 = d; i0 = c; }
            else if (d < b1 || (d == b1 && c < i1)) { b1 = d; i1 = c; }
        }
        int r = row0 + tid;
        g_idxi[r] = i0;
        if (__fsub_rn(b1, b0) < TH_MARGIN) {
            int u = atomicAdd(&g_ucount, 1);
            g_urows[u] = r;
            #pragma unroll 8
            for (int q = 0; q < 32; q++) g_ucand[u * 32 + q] = tI[tid * 32 + q];
        }
    }
}

// ============================================================
// K4: exact rescore of flagged rows (R0-identical numerics), 32 candidates
// ============================================================
__global__ void k_rescore(const float* __restrict__ z, const float* __restrict__ emb) {
    int t = blockIdx.x * blockDim.x + threadIdx.x;
    if (t >= g_ucount) return;
    int r = g_urows[t];
    const float* zr = z + (size_t)r * E_DIM;
    float zn = g_zn[r];
    float bd = 3.4e38f;
    int   bi = 0x7FFFFFFF;
    #pragma unroll 1
    for (int q = 0; q < 32; q++) {
        int c = g_ucand[t * 32 + q];
        const float* er = emb + (size_t)c * E_DIM;
        float acc = 0.0f;
        #pragma unroll 8
        for (int k = 0; k < E_DIM; k++) acc = __fmaf_rn(zr[k], er[k], acc);
        float d = __fsub_rn(__fadd_rn(zn, g_eN[c]), __fmul_rn(2.0f, acc));
        if (d < bd || (d == bd && c < bi)) { bd = d; bi = c; }
    }
    g_idxi[r] = bi;
}

// ============================================================
// K5: epilogue — 512 threads, 4 threads per row
// ============================================================
__global__ __launch_bounds__(512)
void k_epi(const float* __restrict__ z, const float* __restrict__ emb,
           float* __restrict__ out_zq, float* __restrict__ out_idx) {
    __shared__ float sl[512];
    int tid = threadIdx.x;
    int row0 = blockIdx.x * 128;
    int r = row0 + (tid >> 2);
    int h = tid & 3;
    int bi = g_idxi[r];
    if (h == 0) { out_idx[r] = (float)bi; atomicAdd(&g_bins[bi], 1.0f); }
    const float4* zr = (const float4*)(z + (size_t)r * E_DIM + h * 64);
    const float4* er = (const float4*)(emb + (size_t)bi * E_DIM + h * 64);
    float4* oq = (float4*)(out_zq + (size_t)r * E_DIM + h * 64);
    float* dw = g_dw + (size_t)bi * E_DIM + h * 64;
    float ls = 0.0f;
    #pragma unroll 4
    for (int d4 = 0; d4 < 16; d4++) {
        float4 zv = zr[d4];
        float4 ev = er[d4];
        float4 o;
        o.x = __fadd_rn(zv.x, __fsub_rn(ev.x, zv.x));
        o.y = __fadd_rn(zv.y, __fsub_rn(ev.y, zv.y));
        o.z = __fadd_rn(zv.z, __fsub_rn(ev.z, zv.z));
        o.w = __fadd_rn(zv.w, __fsub_rn(ev.w, zv.w));
        oq[d4] = o;
        float dx = __fsub_rn(zv.x, ev.x);
        float dy = __fsub_rn(zv.y, ev.y);
        float dz = __fsub_rn(zv.z, ev.z);
        float dwv = __fsub_rn(zv.w, ev.w);
        ls = __fadd_rn(ls, __fmul_rn(dx, dx));
        ls = __fadd_rn(ls, __fmul_rn(dy, dy));
        ls = __fadd_rn(ls, __fmul_rn(dz, dz));
        ls = __fadd_rn(ls, __fmul_rn(dwv, dwv));
        atomicAdd(dw + d4 * 4 + 0, zv.x);
        atomicAdd(dw + d4 * 4 + 1, zv.y);
        atomicAdd(dw + d4 * 4 + 2, zv.z);
        atomicAdd(dw + d4 * 4 + 3, zv.w);
    }
    sl[tid] = ls;
    __syncthreads();
    for (int s = 256; s > 0; s >>= 1) {
        if (tid < s) sl[tid] += sl[tid + s];
        __syncthreads();
    }
    if (tid == 0) atomicAdd(&g_loss, sl[0]);
}

// ============================================================
// K6: finalize new_embeddings + loss
// ============================================================
__global__ void k_final(float* __restrict__ out_nemb, float* __restrict__ out_loss) {
    int gid = blockIdx.x * blockDim.x + threadIdx.x;
    if (gid == 0) {
        float mean = __fdiv_rn(g_loss, 8388608.0f);
        out_loss[0] = __fmul_rn(0.25f, mean);
    }
    if (gid < N_E * E_DIM) {
        int k = gid >> 8;
        float b = g_bins[k];
        float t1 = __fadd_rn(b, 1e-5f);
        float cl = __fmul_rn(__fdiv_rn(t1, 32768.08192f), 32768.0f);
        out_nemb[gid] = __fdiv_rn(g_dw[gid], cl);
    }
}

// ============================================================
extern "C" void kernel_launch(void* const* d_in, const int* in_sizes, int n_in,
                              void* d_out, int out_size) {
    const float* z   = (const float*)d_in[0];
    const float* emb = (const float*)d_in[1];
    float* out = (float*)d_out;

    cudaFuncSetAttribute(k_mma, cudaFuncAttributeMaxDynamicSharedMemorySize, SM_DYN);

    k_prep<<<8192, 256>>>(emb);
    k_mma<<<N_TOK / BM, 512, SM_DYN>>>(z);
    k_rescore<<<256, 256>>>(z, emb);
    k_epi<<<N_TOK / 128, 512>>>(z, emb, out + OFF_ZQ, out + OFF_IDX);
    k_final<<<8192, 256>>>(out + OFF_NEMB, out + OFF_LOSS);
}